// round 1
// baseline (speedup 1.0000x reference)
#include <cuda_runtime.h>
#include <cstddef>

// ---------------- problem constants ----------------
#define Dm   1024
#define Hh   16
#define HD   64
#define FFNm 4096
#define SEGm 128
#define LLm  256
#define MMm  4
#define BBm  64
#define UUm  128
#define RRm  32
#define TTm  160            // R + U
#define QQm  161            // R + U + 1 (summary)
#define KKm  420            // M + R + L + U
#define BD   (BBm*Dm)       // 65536
#define NEG_INF_F (-1e8f)
#define EPS_LN 1e-5f

// d_out section offsets (floats)
#define S0_OFF 0u                    // output_utterance 128*BD
#define S1_OFF 8388608u              // output_right_context 32*BD
#define S2_OFF 10485760u             // output_mems 1*BD
#define S3_OFF 10551296u             // new_mems 4*BD
#define S4_OFF 10813440u             // new_lc_key 256*BD
#define S5_OFF 27590656u             // new_lc_val 256*BD

// ---------------- scratch (static device globals; allocation-free) ----------------
__device__ float g_cat[165*BD];                 // [state_mems(4) | ln_rc(32) | ln_utt(128) | summary(1)]
__device__ float g_q[QQm*BD];
__device__ float g_k[KKm*BD];
__device__ float g_v[KKm*BD];
__device__ float g_scores[(size_t)1024*QQm*KKm];
__device__ float g_attn[QQm*BD];
__device__ float g_out[QQm*BD];
__device__ float g_res[TTm*BD];
__device__ float g_ffin[TTm*BD];
__device__ float g_ffh[(size_t)TTm*BBm*FFNm];
__device__ float g_ff2[TTm*BD];

// ---------------- reductions ----------------
__device__ __forceinline__ float block_sum_256(float v, float* sh) {
    int lane = threadIdx.x & 31, w = threadIdx.x >> 5;
#pragma unroll
    for (int o = 16; o; o >>= 1) v += __shfl_xor_sync(0xffffffffu, v, o);
    if (lane == 0) sh[w] = v;
    __syncthreads();
    if (w == 0) {
        float r = (lane < 8) ? sh[lane] : 0.0f;
#pragma unroll
        for (int o = 4; o; o >>= 1) r += __shfl_xor_sync(0xffffffffu, r, o);
        if (lane == 0) sh[0] = r;
    }
    __syncthreads();
    float out = sh[0];
    __syncthreads();
    return out;
}

// ---------------- LayerNorm kernels (one block per 1024-elem row, 256 thr) ----------------
__global__ void __launch_bounds__(256) k_ln_in(const float* __restrict__ rc,
                                               const float* __restrict__ utt,
                                               const float* __restrict__ gw,
                                               const float* __restrict__ bw) {
    __shared__ float sh[8];
    int row = blockIdx.x;  // 0..10239  (= t*64 + b over concat(rc, utt))
    const float* src = (row < RRm*BBm) ? rc + (size_t)row*Dm
                                       : utt + (size_t)(row - RRm*BBm)*Dm;
    float* dst = g_cat + (size_t)(4*BBm + row)*Dm;
    int tid = threadIdx.x;
    float4 x = ((const float4*)src)[tid];
    float mu = block_sum_256(x.x + x.y + x.z + x.w, sh) * (1.0f/Dm);
    float dx0 = x.x-mu, dx1 = x.y-mu, dx2 = x.z-mu, dx3 = x.w-mu;
    float var = block_sum_256(dx0*dx0 + dx1*dx1 + dx2*dx2 + dx3*dx3, sh) * (1.0f/Dm);
    float inv = rsqrtf(var + EPS_LN);
    float4 g4 = ((const float4*)gw)[tid], b4 = ((const float4*)bw)[tid];
    float4 o;
    o.x = dx0*inv*g4.x + b4.x; o.y = dx1*inv*g4.y + b4.y;
    o.z = dx2*inv*g4.z + b4.z; o.w = dx3*inv*g4.w + b4.w;
    ((float4*)dst)[tid] = o;
}

__global__ void __launch_bounds__(256) k_ln_ff(const float* __restrict__ gw,
                                               const float* __restrict__ bw) {
    __shared__ float sh[8];
    int row = blockIdx.x;  // 0..10239
    const float* src = g_res + (size_t)row*Dm;
    float* dst = g_ffin + (size_t)row*Dm;
    int tid = threadIdx.x;
    float4 x = ((const float4*)src)[tid];
    float mu = block_sum_256(x.x + x.y + x.z + x.w, sh) * (1.0f/Dm);
    float dx0 = x.x-mu, dx1 = x.y-mu, dx2 = x.z-mu, dx3 = x.w-mu;
    float var = block_sum_256(dx0*dx0 + dx1*dx1 + dx2*dx2 + dx3*dx3, sh) * (1.0f/Dm);
    float inv = rsqrtf(var + EPS_LN);
    float4 g4 = ((const float4*)gw)[tid], b4 = ((const float4*)bw)[tid];
    float4 o;
    o.x = dx0*inv*g4.x + b4.x; o.y = dx1*inv*g4.y + b4.y;
    o.z = dx2*inv*g4.z + b4.z; o.w = dx3*inv*g4.w + b4.w;
    ((float4*)dst)[tid] = o;
}

// final: LN(res + ff2) -> d_out sections 0/1 (rows t<32 -> right_context section)
__global__ void __launch_bounds__(256) k_ln_final(const float* __restrict__ gw,
                                                  const float* __restrict__ bw,
                                                  float* __restrict__ dout) {
    __shared__ float sh[8];
    int row = blockIdx.x;  // 0..10239
    int tid = threadIdx.x;
    float4 a = ((const float4*)(g_res + (size_t)row*Dm))[tid];
    float4 f = ((const float4*)(g_ff2 + (size_t)row*Dm))[tid];
    float4 x; x.x = a.x+f.x; x.y = a.y+f.y; x.z = a.z+f.z; x.w = a.w+f.w;
    float mu = block_sum_256(x.x + x.y + x.z + x.w, sh) * (1.0f/Dm);
    float dx0 = x.x-mu, dx1 = x.y-mu, dx2 = x.z-mu, dx3 = x.w-mu;
    float var = block_sum_256(dx0*dx0 + dx1*dx1 + dx2*dx2 + dx3*dx3, sh) * (1.0f/Dm);
    float inv = rsqrtf(var + EPS_LN);
    float4 g4 = ((const float4*)gw)[tid], b4 = ((const float4*)bw)[tid];
    float4 o;
    o.x = dx0*inv*g4.x + b4.x; o.y = dx1*inv*g4.y + b4.y;
    o.z = dx2*inv*g4.z + b4.z; o.w = dx3*inv*g4.w + b4.w;
    float* dst = (row < RRm*BBm) ? dout + S1_OFF + (size_t)row*Dm
                                 : dout + S0_OFF + (size_t)(row - RRm*BBm)*Dm;
    ((float4*)dst)[tid] = o;
}

// ---------------- summary = mean over utterance LN rows ----------------
__global__ void k_summary() {
    int e = blockIdx.x*blockDim.x + threadIdx.x;  // 0..65535 (b*D + d)
    float s = 0.0f;
#pragma unroll 8
    for (int t = 0; t < UUm; t++) s += g_cat[(size_t)(36 + t)*BD + e];
    g_cat[(size_t)164*BD + e] = s * (1.0f/SEGm);
}

// ---------------- generic GEMM NT:  C = alpha*(A @ W^T) + bias, optional relu ----
// A: M x K (row-major, lda), W: N x K (row-major, ldw). BM=128, BN=64, BK=16, 256 thr.
// K must be a multiple of 16, lda/ldw multiples of 4 (float4 loads).
__global__ void __launch_bounds__(256) gemm_nt(
    const float* __restrict__ A, int lda, long sAz,
    const float* __restrict__ W, int ldw, long sWz,
    const float* __restrict__ bias,
    float* __restrict__ C, int ldc, long sCz,
    int M, int N, int K, float alpha, int relu)
{
    __shared__ float As[16][132];
    __shared__ float Ws[16][68];
    A += (long)blockIdx.z * sAz; W += (long)blockIdx.z * sWz; C += (long)blockIdx.z * sCz;
    const int bm0 = blockIdx.y * 128, bn0 = blockIdx.x * 64;
    const int tid = threadIdx.x;
    const int tx = tid & 15, ty = tid >> 4;
    const int ar = tid >> 1, ak = (tid & 1) * 8;     // A loader: 128 rows x (2x float4)
    const int wr = tid >> 2, wk = (tid & 3) * 4;     // W loader: 64 rows x float4
    const bool avalid = (bm0 + ar) < M;
    const bool wvalid = (bn0 + wr) < N;
    const float* Aptr = A + (size_t)(bm0 + ar)*lda + ak;
    const float* Wptr = W + (size_t)(bn0 + wr)*ldw + wk;

    float acc[8][4];
#pragma unroll
    for (int i = 0; i < 8; i++)
#pragma unroll
        for (int j = 0; j < 4; j++) acc[i][j] = 0.0f;

    for (int k0 = 0; k0 < K; k0 += 16) {
        float4 a0 = make_float4(0,0,0,0), a1 = make_float4(0,0,0,0), w0 = make_float4(0,0,0,0);
        if (avalid) { a0 = *(const float4*)(Aptr + k0); a1 = *(const float4*)(Aptr + k0 + 4); }
        if (wvalid)   w0 = *(const float4*)(Wptr + k0);
        As[ak+0][ar]=a0.x; As[ak+1][ar]=a0.y; As[ak+2][ar]=a0.z; As[ak+3][ar]=a0.w;
        As[ak+4][ar]=a1.x; As[ak+5][ar]=a1.y; As[ak+6][ar]=a1.z; As[ak+7][ar]=a1.w;
        Ws[wk+0][wr]=w0.x; Ws[wk+1][wr]=w0.y; Ws[wk+2][wr]=w0.z; Ws[wk+3][wr]=w0.w;
        __syncthreads();
#pragma unroll
        for (int kk = 0; kk < 16; kk++) {
            float4 af0 = *(const float4*)&As[kk][ty*8];
            float4 af1 = *(const float4*)&As[kk][ty*8 + 4];
            float4 bf  = *(const float4*)&Ws[kk][tx*4];
            float av[8] = {af0.x,af0.y,af0.z,af0.w,af1.x,af1.y,af1.z,af1.w};
            float bv[4] = {bf.x,bf.y,bf.z,bf.w};
#pragma unroll
            for (int i = 0; i < 8; i++)
#pragma unroll
                for (int j = 0; j < 4; j++) acc[i][j] += av[i]*bv[j];
        }
        __syncthreads();
    }
#pragma unroll
    for (int i = 0; i < 8; i++) {
        int r = bm0 + ty*8 + i;
        if (r >= M) continue;
#pragma unroll
        for (int j = 0; j < 4; j++) {
            int c = bn0 + tx*4 + j;
            if (c >= N) continue;
            float v = acc[i][j] * alpha;
            if (bias) v += bias[c];
            if (relu) v = fmaxf(v, 0.0f);
            C[(size_t)r*ldc + c] = v;
        }
    }
}

// ---------------- generic GEMM NN: C = A @ B  (used for P @ V) --------------------
// A: M x K (lda), B: K x N (ldb). K may be non-multiple of 16 but multiple of 4.
__global__ void __launch_bounds__(256) gemm_nn(
    const float* __restrict__ A, int lda, long sAz,
    const float* __restrict__ Bm, int ldb, long sBz,
    float* __restrict__ C, int ldc, long sCz,
    int M, int N, int K)
{
    __shared__ float As[16][132];
    __shared__ float Bs[16][68];
    A += (long)blockIdx.z * sAz; Bm += (long)blockIdx.z * sBz; C += (long)blockIdx.z * sCz;
    const int bm0 = blockIdx.y * 128, bn0 = blockIdx.x * 64;
    const int tid = threadIdx.x;
    const int tx = tid & 15, ty = tid >> 4;
    const int ar = tid >> 1, ak = (tid & 1) * 8;
    const int br = tid >> 4, bc = (tid & 15) * 4;
    const bool avalid = (bm0 + ar) < M;
    const bool bnvalid = (bn0 + bc) < N;
    const float* Aptr = A + (size_t)(bm0 + ar)*lda + ak;

    float acc[8][4];
#pragma unroll
    for (int i = 0; i < 8; i++)
#pragma unroll
        for (int j = 0; j < 4; j++) acc[i][j] = 0.0f;

    for (int k0 = 0; k0 < K; k0 += 16) {
        float4 a0 = make_float4(0,0,0,0), a1 = make_float4(0,0,0,0), b0 = make_float4(0,0,0,0);
        if (avalid) {
            if (k0 + ak     < K) a0 = *(const float4*)(Aptr + k0);
            if (k0 + ak + 4 < K) a1 = *(const float4*)(Aptr + k0 + 4);
        }
        if ((k0 + br) < K && bnvalid)
            b0 = *(const float4*)(Bm + (size_t)(k0 + br)*ldb + bn0 + bc);
        As[ak+0][ar]=a0.x; As[ak+1][ar]=a0.y; As[ak+2][ar]=a0.z; As[ak+3][ar]=a0.w;
        As[ak+4][ar]=a1.x; As[ak+5][ar]=a1.y; As[ak+6][ar]=a1.z; As[ak+7][ar]=a1.w;
        Bs[br][bc+0]=b0.x; Bs[br][bc+1]=b0.y; Bs[br][bc+2]=b0.z; Bs[br][bc+3]=b0.w;
        __syncthreads();
#pragma unroll
        for (int kk = 0; kk < 16; kk++) {
            float4 af0 = *(const float4*)&As[kk][ty*8];
            float4 af1 = *(const float4*)&As[kk][ty*8 + 4];
            float4 bf  = *(const float4*)&Bs[kk][tx*4];
            float av[8] = {af0.x,af0.y,af0.z,af0.w,af1.x,af1.y,af1.z,af1.w};
            float bv[4] = {bf.x,bf.y,bf.z,bf.w};
#pragma unroll
            for (int i = 0; i < 8; i++)
#pragma unroll
                for (int j = 0; j < 4; j++) acc[i][j] += av[i]*bv[j];
        }
        __syncthreads();
    }
#pragma unroll
    for (int i = 0; i < 8; i++) {
        int r = bm0 + ty*8 + i;
        if (r >= M) continue;
#pragma unroll
        for (int j = 0; j < 4; j++) {
            int c = bn0 + tx*4 + j;
            if (c >= N) continue;
            C[(size_t)r*ldc + c] = acc[i][j];
        }
    }
}

// ---------------- masked softmax over K=420, one block per (bh, q) row ------------
__global__ void __launch_bounds__(128) k_softmax(const int* __restrict__ past_len) {
    __shared__ float sred[4];
    int idx = blockIdx.x;
    int q  = idx % QQm;
    int bh = idx / QQm;
    float* row = g_scores + (size_t)bh*(QQm*KKm) + (size_t)q*KKm;
    int pl   = past_len[0];
    int m_kv = min(LLm, pl);
    int m_m  = min(MMm, pl / SEGm);
    int tid = threadIdx.x, lane = tid & 31, w = tid >> 5;

    float v[4];
    float mx = -3.4e38f;
#pragma unroll
    for (int j = 0; j < 4; j++) {
        int c = tid + 128*j;
        float val = -3.4e38f;
        if (c < KKm) {
            bool msk = (c < MMm - m_m) ||
                       (c >= MMm + RRm && c < MMm + RRm + (LLm - m_kv)) ||
                       (q == QQm - 1 && c < MMm);
            val = msk ? NEG_INF_F : row[c];
        }
        v[j] = val;
        mx = fmaxf(mx, val);
    }
#pragma unroll
    for (int o = 16; o; o >>= 1) mx = fmaxf(mx, __shfl_xor_sync(0xffffffffu, mx, o));
    if (lane == 0) sred[w] = mx;
    __syncthreads();
    mx = fmaxf(fmaxf(sred[0], sred[1]), fmaxf(sred[2], sred[3]));
    __syncthreads();

    float s = 0.0f;
#pragma unroll
    for (int j = 0; j < 4; j++) {
        int c = tid + 128*j;
        if (c < KKm) { v[j] = expf(v[j] - mx); s += v[j]; }
    }
#pragma unroll
    for (int o = 16; o; o >>= 1) s += __shfl_xor_sync(0xffffffffu, s, o);
    if (lane == 0) sred[w] = s;
    __syncthreads();
    s = sred[0] + sred[1] + sred[2] + sred[3];
    float r = 1.0f / s;
#pragma unroll
    for (int j = 0; j < 4; j++) {
        int c = tid + 128*j;
        if (c < KKm) row[c] = v[j] * r;
    }
}

// ---------------- residual add, clip ----------------
__global__ void k_resadd(const float* __restrict__ rc, const float* __restrict__ utt) {
    size_t i = (size_t)blockIdx.x*blockDim.x + threadIdx.x;     // float4 index, n4 = 160*BD/4
    float4 o = ((const float4*)g_out)[i];
    size_t rc4 = (size_t)RRm*BD/4;
    float4 s = (i < rc4) ? ((const float4*)rc)[i] : ((const float4*)utt)[i - rc4];
    float4 r; r.x = o.x+s.x; r.y = o.y+s.y; r.z = o.z+s.z; r.w = o.w+s.w;
    ((float4*)g_res)[i] = r;
}

__global__ void k_clip(float* __restrict__ dout) {
    size_t i = (size_t)blockIdx.x*blockDim.x + threadIdx.x;     // float4 index over BD/4
    float4 v = ((const float4*)(g_out + (size_t)TTm*BD))[i];
    v.x = fminf(fmaxf(v.x, -10.f), 10.f);
    v.y = fminf(fmaxf(v.y, -10.f), 10.f);
    v.z = fminf(fmaxf(v.z, -10.f), 10.f);
    v.w = fminf(fmaxf(v.w, -10.f), 10.f);
    ((float4*)(dout + S2_OFF))[i] = v;
}

// ---------------- launcher ----------------
extern "C" void kernel_launch(void* const* d_in, const int* in_sizes, int n_in,
                              void* d_out_v, int out_size) {
    const float* utterance   = (const float*)d_in[0];
    const float* right_ctx   = (const float*)d_in[1];
    const float* mems_in     = (const float*)d_in[2];
    const float* state_mems  = (const float*)d_in[3];
    const float* lc_key      = (const float*)d_in[4];
    const float* lc_val      = (const float*)d_in[5];
    const float* W_kv        = (const float*)d_in[6];
    const float* b_kv        = (const float*)d_in[7];
    const float* W_q         = (const float*)d_in[8];
    const float* b_q         = (const float*)d_in[9];
    const float* W_out       = (const float*)d_in[10];
    const float* b_out       = (const float*)d_in[11];
    const float* ln_in_g     = (const float*)d_in[12];
    const float* ln_in_b     = (const float*)d_in[13];
    const float* ln_ff_g     = (const float*)d_in[14];
    const float* ln_ff_b     = (const float*)d_in[15];
    const float* W_ff1       = (const float*)d_in[16];
    const float* b_ff1       = (const float*)d_in[17];
    const float* W_ff2       = (const float*)d_in[18];
    const float* b_ff2       = (const float*)d_in[19];
    const float* ln_out_g    = (const float*)d_in[20];
    const float* ln_out_b    = (const float*)d_in[21];
    const int*   past_len    = (const int*)  d_in[22];
    float* dout = (float*)d_out_v;

    float *cat, *q, *k, *v, *scores, *attn, *outb, *ffin, *ffh, *ff2b;
    cudaGetSymbolAddress((void**)&cat,    g_cat);
    cudaGetSymbolAddress((void**)&q,      g_q);
    cudaGetSymbolAddress((void**)&k,      g_k);
    cudaGetSymbolAddress((void**)&v,      g_v);
    cudaGetSymbolAddress((void**)&scores, g_scores);
    cudaGetSymbolAddress((void**)&attn,   g_attn);
    cudaGetSymbolAddress((void**)&outb,   g_out);
    cudaGetSymbolAddress((void**)&ffin,   g_ffin);
    cudaGetSymbolAddress((void**)&ffh,    g_ffh);
    cudaGetSymbolAddress((void**)&ff2b,   g_ff2);

    // 1. state_mems -> g_cat rows 0..3
    cudaMemcpyAsync(cat, state_mems, (size_t)4*BD*sizeof(float),
                    cudaMemcpyDeviceToDevice, 0);
    // 2. LN over concat(rc, utt) -> g_cat rows 4..163
    k_ln_in<<<TTm*BBm, 256>>>(right_ctx, utterance, ln_in_g, ln_in_b);
    // 3. summary -> g_cat row 164
    k_summary<<<BD/256, 256>>>();

    // 4. query = q_in @ W_q^T + b_q      (q_in = g_cat rows 4..164, M = 161*64)
    gemm_nt<<<dim3(16, 81, 1), 256>>>(cat + (size_t)4*BD, Dm, 0, W_q, Dm, 0, b_q,
                                      q, Dm, 0, QQm*BBm, Dm, Dm, 1.0f, 0);
    // 5-8. k_all / v_all split directly into g_k/g_v (rows 0..35 and 292..419)
    gemm_nt<<<dim3(16, 18, 1), 256>>>(cat, Dm, 0, W_kv, Dm, 0, b_kv,
                                      k, Dm, 0, 36*BBm, Dm, Dm, 1.0f, 0);
    gemm_nt<<<dim3(16, 64, 1), 256>>>(cat + (size_t)36*BD, Dm, 0, W_kv, Dm, 0, b_kv,
                                      k + (size_t)292*BD, Dm, 0, UUm*BBm, Dm, Dm, 1.0f, 0);
    gemm_nt<<<dim3(16, 18, 1), 256>>>(cat, Dm, 0, W_kv + (size_t)Dm*Dm, Dm, 0, b_kv + Dm,
                                      v, Dm, 0, 36*BBm, Dm, Dm, 1.0f, 0);
    gemm_nt<<<dim3(16, 64, 1), 256>>>(cat + (size_t)36*BD, Dm, 0, W_kv + (size_t)Dm*Dm, Dm, 0, b_kv + Dm,
                                      v + (size_t)292*BD, Dm, 0, UUm*BBm, Dm, Dm, 1.0f, 0);
    // 9-10. cached local-context K/V into the middle
    cudaMemcpyAsync(k + (size_t)36*BD, lc_key, (size_t)LLm*BD*sizeof(float),
                    cudaMemcpyDeviceToDevice, 0);
    cudaMemcpyAsync(v + (size_t)36*BD, lc_val, (size_t)LLm*BD*sizeof(float),
                    cudaMemcpyDeviceToDevice, 0);

    // 11. scores = 0.125 * Qh @ Kh^T   (batched over bh=1024)
    gemm_nt<<<dim3(7, 2, 1024), 256>>>(q, BD, 64, k, BD, 64, nullptr,
                                       scores, KKm, (long)QQm*KKm,
                                       QQm, KKm, HD, 0.125f, 0);
    // 12. masked softmax
    k_softmax<<<1024*QQm, 128>>>(past_len);
    // 13. attn = P @ Vh  (batched)
    gemm_nn<<<dim3(1, 2, 1024), 256>>>(scores, KKm, (long)QQm*KKm, v, BD, 64,
                                       attn, BD, 64, QQm, HD, KKm);
    // 14. out = attn @ W_out^T + b_out
    gemm_nt<<<dim3(16, 81, 1), 256>>>(attn, Dm, 0, W_out, Dm, 0, b_out,
                                      outb, Dm, 0, QQm*BBm, Dm, Dm, 1.0f, 0);
    // 15. residual, 16. clipped mems output
    k_resadd<<<(TTm*BD/4)/256, 256>>>(right_ctx, utterance);
    k_clip<<<(BD/4)/256, 256>>>(dout);
    // 17. LN for FFN
    k_ln_ff<<<TTm*BBm, 256>>>(ln_ff_g, ln_ff_b);
    // 18-19. FFN
    gemm_nt<<<dim3(64, 80, 1), 256>>>(ffin, Dm, 0, W_ff1, Dm, 0, b_ff1,
                                      ffh, FFNm, 0, TTm*BBm, FFNm, Dm, 1.0f, 1);
    gemm_nt<<<dim3(16, 80, 1), 256>>>(ffh, FFNm, 0, W_ff2, FFNm, 0, b_ff2,
                                      ff2b, Dm, 0, TTm*BBm, Dm, FFNm, 1.0f, 0);
    // 20. final LN -> output_utterance / output_right_context
    k_ln_final<<<TTm*BBm, 256>>>(ln_out_g, ln_out_b, dout);

    // 21+. state-carry outputs
    cudaMemcpyAsync(dout + S3_OFF, state_mems + BD, (size_t)3*BD*sizeof(float),
                    cudaMemcpyDeviceToDevice, 0);
    cudaMemcpyAsync(dout + S3_OFF + (size_t)3*BD, mems_in, (size_t)BD*sizeof(float),
                    cudaMemcpyDeviceToDevice, 0);
    cudaMemcpyAsync(dout + S4_OFF, lc_key + (size_t)128*BD, (size_t)128*BD*sizeof(float),
                    cudaMemcpyDeviceToDevice, 0);
    cudaMemcpyAsync(dout + S4_OFF + (size_t)128*BD, k + (size_t)292*BD,
                    (size_t)128*BD*sizeof(float), cudaMemcpyDeviceToDevice, 0);
    cudaMemcpyAsync(dout + S5_OFF, lc_val + (size_t)128*BD, (size_t)128*BD*sizeof(float),
                    cudaMemcpyDeviceToDevice, 0);
    cudaMemcpyAsync(dout + S5_OFF + (size_t)128*BD, v + (size_t)292*BD,
                    (size_t)128*BD*sizeof(float), cudaMemcpyDeviceToDevice, 0);
}